// round 17
// baseline (speedup 1.0000x reference)
#include <cuda_runtime.h>
#include <cuda_fp16.h>
#include <cstdint>

#define B_    4
#define CIN_  256
#define P_    4096
#define RDIM  2304          // CIN*9, reordered as r' = k*256 + c
#define COUT_ 256
#define NTOT  16384
#define XTOT  (B_ * CIN_ * P_)     // 4,194,304
#define XHALF (XTOT / 2)           // 2,097,152

// ---------------------------------------------------------------------------
// Device scratch (static — no cudaMalloc allowed)
// ---------------------------------------------------------------------------
// fp16 pair copies of x: [0:XHALF) even-start pairs, [XHALF:2*XHALF) odd-start
__device__ __align__(128) uint32_t g_xpair[XTOT];
// fp16 weights, PERMUTED: g_wh[o*2304 + k*256 + c] = w[o][c][k]
__device__ __align__(128) __half g_wh[COUT_ * RDIM];

__device__ __forceinline__ uint32_t smem_u32(const void* p) {
    uint32_t a;
    asm("{ .reg .u64 t; cvta.to.shared.u64 t, %1; cvt.u32.u64 %0, t; }"
        : "=r"(a) : "l"(p));
    return a;
}

#define CP16(dst, src) \
    asm volatile("cp.async.cg.shared.global [%0], [%1], 16;" \
                 :: "r"(dst), "l"(src) : "memory")
#define CP_COMMIT() asm volatile("cp.async.commit_group;" ::: "memory")
#define CP_WAIT1()  asm volatile("cp.async.wait_group 1;" ::: "memory")

#define LDMX4(r0, r1, r2, r3, a) \
    asm volatile("ldmatrix.sync.aligned.m8n8.x4.shared.b16 {%0,%1,%2,%3}, [%4];" \
                 : "=r"(r0), "=r"(r1), "=r"(r2), "=r"(r3) : "r"(a))
#define LDMX4T(r0, r1, r2, r3, a) \
    asm volatile("ldmatrix.sync.aligned.m8n8.x4.trans.shared.b16 {%0,%1,%2,%3}, [%4];" \
                 : "=r"(r0), "=r"(r1), "=r"(r2), "=r"(r3) : "r"(a))

#define MMA16816F(d, a, b0, b1) \
    asm volatile("mma.sync.aligned.m16n8k16.row.col.f32.f16.f16.f32 " \
                 "{%0,%1,%2,%3},{%4,%5,%6,%7},{%8,%9},{%0,%1,%2,%3};" \
                 : "+f"((d)[0]), "+f"((d)[1]), "+f"((d)[2]), "+f"((d)[3]) \
                 : "r"((a)[0]), "r"((a)[1]), "r"((a)[2]), "r"((a)[3]), \
                   "r"(b0), "r"(b1))

__device__ __forceinline__ uint32_t pk_h2(__half a, __half b) {
    return (uint32_t)__half_as_ushort(a) | ((uint32_t)__half_as_ushort(b) << 16);
}

// ---------------------------------------------------------------------------
// Kernel 0: build fp16 paired x copies + permuted fp16 weights
// ---------------------------------------------------------------------------
__global__ __launch_bounds__(256) void prep_kernel(
    const float* __restrict__ x, const float* __restrict__ weight)
{
    const size_t t = (size_t)blockIdx.x * 256 + threadIdx.x;   // < 1,048,576
    const size_t e = t * 4;
    float4 f = *(const float4*)(x + e);
    float e4 = (e + 4 < XTOT) ? __ldg(x + e + 4) : f.w;

    __half hx = __float2half_rn(f.x), hy = __float2half_rn(f.y);
    __half hz = __float2half_rn(f.z), hw = __float2half_rn(f.w);
    __half h4 = __float2half_rn(e4);

    *(uint2*)(g_xpair + 2 * t)         = make_uint2(pk_h2(hx, hy), pk_h2(hz, hw));
    *(uint2*)(g_xpair + XHALF + 2 * t) = make_uint2(pk_h2(hy, hz), pk_h2(hw, h4));

    // weight permute+convert: 589,824 = 4 * 147,456
    if (t < 147456) {
        float4 w = *(const float4*)(weight + 4 * t);
        float wv[4] = {w.x, w.y, w.z, w.w};
        #pragma unroll
        for (int q = 0; q < 4; q++) {
            int flat = (int)(4 * t) + q;
            int o = flat / 2304, rem = flat % 2304;
            int c = rem / 9, kk = rem % 9;
            g_wh[o * 2304 + kk * 256 + c] = __float2half_rn(wv[q]);
        }
    }
}

// ---------------------------------------------------------------------------
// Kernel 1: FUSED sampled-im2col + fp16 GEMM
//   CTA: M=256 (all Cout) x N=128 (p-slice). K-chunk 64 = (k fixed, 64 c's).
//   512 threads, 16 warps (4x4), warp tile 64x32.
//   B tiles produced in-kernel (triple buffer); A via cp.async (3 stages).
// ---------------------------------------------------------------------------
#define BK      64
#define NCH     36
#define BN      128
#define A_STRIDE 144
#define B_STRIDE 272
// params SoA (1152 = 9 k x 128 p entries)
#define PAR_IDX0 0
#define PAR_IDX1 4608
#define PAR_W0   9216
#define PAR_W1   13824
#define PAR_W2   18432
#define PAR_W3   23040
#define PARAMS_BYTES 27648
#define OFF_A   PARAMS_BYTES                  // 27648
#define A_STAGE (256 * A_STRIDE)              // 36864
#define OFF_B   (OFF_A + 3 * A_STAGE)         // 138240
#define B_BUF   (64 * B_STRIDE)               // 17408
#define SMEM_TOTAL (OFF_B + 3 * B_BUF)        // 190464

__global__ __launch_bounds__(512, 1) void fused_kernel(
    const float* __restrict__ offset, const float* __restrict__ mask,
    const float* __restrict__ bias, float* __restrict__ out)
{
    extern __shared__ char smem[];
    const uint32_t sb0 = smem_u32(smem);
    const int tid = threadIdx.x;
    const int lane = tid & 31, wid = tid >> 5;
    const int warp_m = wid >> 2;          // 0..3 -> m offset *64
    const int warp_n = wid & 3;           // 0..3 -> n offset *32
    const int n0 = blockIdx.x * BN;
    const int bb = n0 >> 12, p0g = n0 & 4095;

    // ---- sampling params for (k, p-local): 1152 entries
    for (int e = tid; e < 1152; e += 512) {
        int k = e >> 7, pl = e & 127;
        int p = p0g + pl;
        int oy = p >> 6, ox = p & 63;
        int kh = k / 3, kw = k - kh * 3;
        float dy = __ldg(offset + (bb * 18 + 2 * k) * P_ + p);
        float dx = __ldg(offset + (bb * 18 + 2 * k + 1) * P_ + p);
        float m  = __ldg(mask + (bb * 9 + k) * P_ + p);

        float sy = (float)(oy - 1 + kh) + dy;
        float sx = (float)(ox - 1 + kw) + dx;
        float y0f = floorf(sy), x0f = floorf(sx);
        float wy = sy - y0f,    wx = sx - x0f;
        int y0 = (int)y0f, x0 = (int)x0f;
        int y1 = y0 + 1,   x1 = x0 + 1;

        bool vy0 = ((unsigned)y0 < 64u), vy1 = ((unsigned)y1 < 64u);
        bool vx0 = ((unsigned)x0 < 64u), vx1 = ((unsigned)x1 < 64u);
        int cy0 = min(max(y0, 0), 63), cy1 = min(max(y1, 0), 63);
        int cx0 = min(max(x0, 0), 63), cx1 = min(max(x1, 0), 63);
        int cxb = min(max(x0, 0), 62);

        float w00 = (1.f - wy) * (1.f - wx) * m; if (!(vy0 && vx0)) w00 = 0.f;
        float w01 = (1.f - wy) * wx * m;         if (!(vy0 && vx1)) w01 = 0.f;
        float w10 = wy * (1.f - wx) * m;         if (!(vy1 && vx0)) w10 = 0.f;
        float w11 = wy * wx * m;                 if (!(vy1 && vx1)) w11 = 0.f;

        bool e00 = (cx0 == cxb);
        bool e10 = (cx1 == cxb);
        float wA0 = (e00 ? w00 : 0.f) + (e10 ? w01 : 0.f);
        float wB0 = (e00 ? 0.f : w00) + (e10 ? 0.f : w01);
        float wA1 = (e00 ? w10 : 0.f) + (e10 ? w11 : 0.f);
        float wB1 = (e00 ? 0.f : w10) + (e10 ? 0.f : w11);

        uint32_t base = ((cxb & 1) ? XHALF : 0) + (uint32_t)(bb * CIN_) * 2048;
        int j = cxb >> 1;
        uint32_t idx0 = base + cy0 * 32 + j;
        uint32_t idx1 = base + cy1 * 32 + j;

        *(uint32_t*)(smem + PAR_IDX0 + e * 4) = idx0;
        *(uint32_t*)(smem + PAR_IDX1 + e * 4) = idx1;
        *(float*)(smem + PAR_W0 + e * 4) = wA0;
        *(float*)(smem + PAR_W1 + e * 4) = wB0;
        *(float*)(smem + PAR_W2 + e * 4) = wA1;
        *(float*)(smem + PAR_W3 + e * 4) = wB1;
    }

    const int lgrp = lane >> 3, lr = lane & 7;
    const int a_row   = ((lgrp & 1) << 3) + lr;
    const int a_chunk = lgrp >> 1;
    const int b_krow  = ((lgrp & 1) << 3) + lr;
    const int b_col   = (warp_n << 5) + ((lgrp >> 1) << 3);

    const int a_r = tid >> 1, a_h = tid & 1;   // A: 256 rows, 8x16B per row
    const int np = tid & 63, rg = tid >> 6;    // produce: n-pair, row group

    float d[4][4][4];
    #pragma unroll
    for (int i = 0; i < 4; i++)
        #pragma unroll
        for (int j = 0; j < 4; j++)
            #pragma unroll
            for (int q = 0; q < 4; q++) d[i][j][q] = 0.f;

    auto loadA = [&](int ch) {
        const int kc0 = ch * BK;
        const uint32_t st = sb0 + OFF_A + (ch % 3) * A_STAGE;
        #pragma unroll
        for (int q = 0; q < 4; q++) {
            int c16 = a_h + 2 * q;
            CP16(st + a_r * A_STRIDE + c16 * 16,
                 g_wh + (size_t)a_r * RDIM + kc0 + c16 * 8);
        }
    };

    auto produceB = [&](int ch) {
        const int k = ch >> 2, c0c = (ch & 3) * 64;
        const int eA = (k << 7) + 2 * np, eB = eA + 1;
        uint32_t i0a = *(const uint32_t*)(smem + PAR_IDX0 + eA * 4);
        uint32_t i1a = *(const uint32_t*)(smem + PAR_IDX1 + eA * 4);
        float w0a = *(const float*)(smem + PAR_W0 + eA * 4);
        float w1a = *(const float*)(smem + PAR_W1 + eA * 4);
        float w2a = *(const float*)(smem + PAR_W2 + eA * 4);
        float w3a = *(const float*)(smem + PAR_W3 + eA * 4);
        uint32_t i0b = *(const uint32_t*)(smem + PAR_IDX0 + eB * 4);
        uint32_t i1b = *(const uint32_t*)(smem + PAR_IDX1 + eB * 4);
        float w0b = *(const float*)(smem + PAR_W0 + eB * 4);
        float w1b = *(const float*)(smem + PAR_W1 + eB * 4);
        float w2b = *(const float*)(smem + PAR_W2 + eB * 4);
        float w3b = *(const float*)(smem + PAR_W3 + eB * 4);

        const uint32_t boff = OFF_B + (ch % 3) * B_BUF + rg * B_STRIDE + np * 4;
        const int cbase = (c0c + rg) * 2048;
        #pragma unroll 4
        for (int i = 0; i < 8; i++) {
            int coff = cbase + i * (8 * 2048);
            uint32_t q0a = __ldg(g_xpair + i0a + coff);
            uint32_t q1a = __ldg(g_xpair + i1a + coff);
            uint32_t q0b = __ldg(g_xpair + i0b + coff);
            uint32_t q1b = __ldg(g_xpair + i1b + coff);
            float2 f0a = __half22float2(*reinterpret_cast<const __half2*>(&q0a));
            float2 f1a = __half22float2(*reinterpret_cast<const __half2*>(&q1a));
            float2 f0b = __half22float2(*reinterpret_cast<const __half2*>(&q0b));
            float2 f1b = __half22float2(*reinterpret_cast<const __half2*>(&q1b));
            float v0 = w0a * f0a.x + w1a * f0a.y + w2a * f1a.x + w3a * f1a.y;
            float v1 = w0b * f0b.x + w1b * f0b.y + w2b * f1b.x + w3b * f1b.y;
            *(uint32_t*)(smem + boff + i * (8 * B_STRIDE)) =
                pk_h2(__float2half_rn(v0), __float2half_rn(v1));
        }
    };

    __syncthreads();            // params visible
    produceB(0);
    loadA(0); CP_COMMIT();
    loadA(1); CP_COMMIT();

    for (int ch = 0; ch < NCH; ch++) {
        CP_WAIT1();             // A(ch) complete (this thread's portion)
        __syncthreads();        // B(ch) + A(ch) visible; prior MMA reads done
        if (ch + 1 < NCH) produceB(ch + 1);
        if (ch + 2 < NCH) loadA(ch + 2);
        CP_COMMIT();

        const uint32_t stA = sb0 + OFF_A + (ch % 3) * A_STAGE;
        const uint32_t stB = sb0 + OFF_B + (ch % 3) * B_BUF;
        const uint32_t aBase = stA + (warp_m * 64 + a_row) * A_STRIDE + a_chunk * 16;
        const uint32_t bBase = stB + b_krow * B_STRIDE + b_col * 2;

        #pragma unroll
        for (int s = 0; s < 4; s++) {
            uint32_t af[4][4], bf[2][4];
            #pragma unroll
            for (int i = 0; i < 4; i++) {
                uint32_t aa = aBase + i * (16 * A_STRIDE) + s * 32;
                LDMX4(af[i][0], af[i][1], af[i][2], af[i][3], aa);
            }
            #pragma unroll
            for (int g = 0; g < 2; g++) {
                uint32_t ba = bBase + s * (16 * B_STRIDE) + g * 32;
                LDMX4T(bf[g][0], bf[g][1], bf[g][2], bf[g][3], ba);
            }
            #pragma unroll
            for (int i = 0; i < 4; i++)
                #pragma unroll
                for (int g = 0; g < 2; g++)
                    #pragma unroll
                    for (int jn = 0; jn < 2; jn++)
                        MMA16816F(d[i][g * 2 + jn], af[i],
                                  bf[g][jn * 2], bf[g][jn * 2 + 1]);
        }
    }

    // ---- epilogue ----
    const int row0 = lane >> 2, col0 = (lane & 3) * 2;
    const int pbase = p0g + warp_n * 32 + col0;
    #pragma unroll
    for (int i = 0; i < 4; i++) {
        int co = warp_m * 64 + i * 16 + row0;
        float bi0 = __ldg(bias + co);
        float bi1 = __ldg(bias + co + 8);
        float* o0 = out + ((size_t)(bb * COUT_ + co)) * P_ + pbase;
        float* o1 = o0 + 8 * P_;
        #pragma unroll
        for (int j = 0; j < 4; j++) {
            float2 v0 = make_float2(d[i][j][0] + bi0, d[i][j][1] + bi0);
            float2 v1 = make_float2(d[i][j][2] + bi1, d[i][j][3] + bi1);
            *(float2*)(o0 + j * 8) = v0;
            *(float2*)(o1 + j * 8) = v1;
        }
    }
}

// ---------------------------------------------------------------------------
extern "C" void kernel_launch(void* const* d_in, const int* in_sizes, int n_in,
                              void* d_out, int out_size) {
    const float* x      = (const float*)d_in[0];
    const float* offset = (const float*)d_in[1];
    const float* mask   = (const float*)d_in[2];
    const float* weight = (const float*)d_in[3];
    const float* bias   = (const float*)d_in[4];
    float* out = (float*)d_out;

    cudaFuncSetAttribute(fused_kernel,
                         cudaFuncAttributeMaxDynamicSharedMemorySize, SMEM_TOTAL);

    prep_kernel<<<4096, 256>>>(x, weight);
    fused_kernel<<<NTOT / BN, 512, SMEM_TOTAL>>>(offset, mask, bias, out);
}